// round 3
// baseline (speedup 1.0000x reference)
#include <cuda_runtime.h>

#define A_DIM 128
#define B_DIM 128
#define N_DIM 64
#define H_DIM 1024
#define BATCH_N 1024

typedef unsigned long long u64;

__device__ __forceinline__ u64 pack2(float lo, float hi) {
    u64 r;
    asm("mov.b64 %0, {%1, %2};" : "=l"(r) : "f"(lo), "f"(hi));
    return r;
}
__device__ __forceinline__ void fma2(u64& d, u64 a, u64 b) {
    asm("fma.rn.f32x2 %0, %1, %2, %0;" : "+l"(d) : "l"(a), "l"(b));
}

// Normalized, transposed filterbanks. gamma folded into FyT.
__device__ float g_FyT[A_DIM * N_DIM];
__device__ float g_FxT[B_DIM * N_DIM];

__global__ void setup_kernel(const float* __restrict__ h,
                             const float* __restrict__ Ww,
                             const float* __restrict__ Wb) {
    __shared__ float red[256];
    __shared__ float s_params[5];
    __shared__ float s_scal[5];
    int tid = threadIdx.x;

    for (int i = 0; i < 5; i++) {
        float p = 0.f;
        for (int j = tid; j < H_DIM; j += 256) p += Ww[i * H_DIM + j] * h[j];
        red[tid] = p;
        __syncthreads();
        for (int s = 128; s > 0; s >>= 1) {
            if (tid < s) red[tid] += red[tid + s];
            __syncthreads();
        }
        if (tid == 0) s_params[i] = red[0] + Wb[i];
        __syncthreads();
    }

    if (tid == 0) {
        float gtX = s_params[0];
        float gtY = s_params[1];
        float var = expf(s_params[2] + 1e-8f);
        float dd  = expf(s_params[3]) * (float)(A_DIM - 1) / (float)(N_DIM - 1);
        float gamma = expf(s_params[4]);
        s_scal[0] = (float)(A_DIM + 1) * (gtX + 1.f) * 0.5f;
        s_scal[1] = (float)(B_DIM + 1) * (gtY + 1.f) * 0.5f;
        s_scal[2] = dd;
        s_scal[3] = 1.f / (2.f * var);
        s_scal[4] = gamma;
    }
    __syncthreads();
    float gX = s_scal[0], gY = s_scal[1], dd = s_scal[2];
    float i2v = s_scal[3], gamma = s_scal[4];

    float sx = 0.f, sy = 0.f;
    for (int idx = tid; idx < N_DIM * A_DIM; idx += 256) {
        int n = idx >> 7;
        int a = idx & 127;
        float off = ((float)n - (float)N_DIM * 0.5f - 0.5f) * dd;
        float muX = gX + off;
        float muY = gY + off;
        float da = (float)a - muX;
        float db = (float)a - muY;
        float fx = expf(-da * da * i2v);
        float fy = expf(-db * db * i2v);
        g_FxT[a * N_DIM + n] = fx;
        g_FyT[a * N_DIM + n] = fy;
        sx += fx;
        sy += fy;
    }
    red[tid] = sx;
    __syncthreads();
    for (int s = 128; s > 0; s >>= 1) {
        if (tid < s) red[tid] += red[tid + s];
        __syncthreads();
    }
    float sumX = red[0];
    __syncthreads();
    red[tid] = sy;
    __syncthreads();
    for (int s = 128; s > 0; s >>= 1) {
        if (tid < s) red[tid] += red[tid + s];
        __syncthreads();
    }
    float sumY = red[0];
    __syncthreads();

    float invX = 1.f / sumX;
    float invYg = gamma / sumY;
    for (int idx = tid; idx < N_DIM * A_DIM; idx += 256) {
        g_FxT[idx] *= invX;
        g_FyT[idx] *= invYg;
    }
}

#define TSTR 68
// smem floats: fyT 8192 | fxT 8192 | tT 128*TSTR  (~98KB -> 2 blocks/SM)
#define SMEM_FLOATS (16384 + 128 * TSTR)

__global__ __launch_bounds__(256, 2)
void filt_kernel(const float* __restrict__ x,
                 const float* __restrict__ xh,
                 float* __restrict__ out) {
    extern __shared__ float sm[];
    float* fyT = sm;
    float* fxT = sm + 8192;
    float* tT  = sm + 16384;

    int k = blockIdx.x;
    int which = blockIdx.y;
    const float* src = (which == 0 ? x : xh) + (size_t)k * (A_DIM * B_DIM);
    int tid = threadIdx.x;

    // stage filterbanks only (2x32KB), coalesced float4
    {
        const float4* fy4 = (const float4*)g_FyT;
        const float4* fx4 = (const float4*)g_FxT;
        float4* dfy = (float4*)fyT;
        float4* dfx = (float4*)fxT;
#pragma unroll
        for (int i = 0; i < 8; i++) {
            dfy[tid + i * 256] = fy4[tid + i * 256];
            dfx[tid + i * 256] = fx4[tid + i * 256];
        }
    }
    __syncthreads();

    // ---- Stage 1: t[n][b] = sum_a FyT[a][n] * z[a][b]  (packed over n) ----
    // z read straight from global (each element touched once per block),
    // distance-1 register prefetch. thread tile 8n x 4b.
    {
        int b0 = (tid & 3) * 4 + (tid >> 5) * 16;
        int n0 = ((tid >> 2) & 7) * 8;

        const float4* zsrc = (const float4*)src + (b0 >> 2);  // + a*32 per row

        u64 acc[4][4];  // [n-pair][b]
#pragma unroll
        for (int j = 0; j < 4; j++)
#pragma unroll
            for (int i = 0; i < 4; i++) acc[j][i] = 0ull;

        float4 zv = __ldg(zsrc);
#pragma unroll 4
        for (int a = 0; a < A_DIM; a++) {
            float4 znx;
            if (a < A_DIM - 1) znx = __ldg(zsrc + (a + 1) * 32);
            ulonglong2 f01 = *(const ulonglong2*)&fyT[a * 64 + n0];
            ulonglong2 f23 = *(const ulonglong2*)&fyT[a * 64 + n0 + 4];
            u64 fp[4] = {f01.x, f01.y, f23.x, f23.y};
            u64 zb[4] = {pack2(zv.x, zv.x), pack2(zv.y, zv.y),
                         pack2(zv.z, zv.z), pack2(zv.w, zv.w)};
#pragma unroll
            for (int j = 0; j < 4; j++)
#pragma unroll
                for (int i = 0; i < 4; i++) fma2(acc[j][i], fp[j], zb[i]);
            zv = znx;
        }

        // store transposed: tT[b][n0..n0+7]
#pragma unroll
        for (int i = 0; i < 4; i++) {
            int row = b0 + i;
            ulonglong2 s0, s1;
            s0.x = acc[0][i]; s0.y = acc[1][i];
            s1.x = acc[2][i]; s1.y = acc[3][i];
            *(ulonglong2*)&tT[row * TSTR + n0] = s0;
            *(ulonglong2*)&tT[row * TSTR + n0 + 4] = s1;
        }
    }
    __syncthreads();

    // ---- Stage 2: out[n][m] = sum_b tT[b][n] * FxT[b][m]  (packed over m) ----
    {
        int m0 = (tid & 15) * 4;
        int n0 = (tid >> 4) * 4;

        u64 acc[4][2];
#pragma unroll
        for (int j = 0; j < 4; j++) {
            acc[j][0] = 0ull;
            acc[j][1] = 0ull;
        }

#pragma unroll 4
        for (int b = 0; b < B_DIM; b++) {
            float4 tv = *(const float4*)&tT[b * TSTR + n0];
            ulonglong2 fxp = *(const ulonglong2*)&fxT[b * 64 + m0];
            u64 tp[4] = {pack2(tv.x, tv.x), pack2(tv.y, tv.y),
                         pack2(tv.z, tv.z), pack2(tv.w, tv.w)};
#pragma unroll
            for (int j = 0; j < 4; j++) {
                fma2(acc[j][0], tp[j], fxp.x);
                fma2(acc[j][1], tp[j], fxp.y);
            }
        }

        float* obase = out + (size_t)k * (2 * N_DIM * N_DIM) + which * (N_DIM * N_DIM);
#pragma unroll
        for (int j = 0; j < 4; j++) {
            ulonglong2 s;
            s.x = acc[j][0];
            s.y = acc[j][1];
            *(ulonglong2*)&obase[(n0 + j) * N_DIM + m0] = s;
        }
    }
}

extern "C" void kernel_launch(void* const* d_in, const int* in_sizes, int n_in,
                              void* d_out, int out_size) {
    const float* x  = (const float*)d_in[0];
    const float* xh = (const float*)d_in[1];
    const float* h  = (const float*)d_in[2];
    const float* Ww = (const float*)d_in[3];
    const float* Wb = (const float*)d_in[4];
    float* out = (float*)d_out;

    cudaFuncSetAttribute(filt_kernel, cudaFuncAttributeMaxDynamicSharedMemorySize,
                         SMEM_FLOATS * sizeof(float));

    setup_kernel<<<1, 256>>>(h, Ww, Wb);

    dim3 grid(BATCH_N, 2);
    filt_kernel<<<grid, 256, SMEM_FLOATS * sizeof(float)>>>(x, xh, out);
}

// round 4
// speedup vs baseline: 1.0248x; 1.0248x over previous
#include <cuda_runtime.h>

#define A_DIM 128
#define B_DIM 128
#define N_DIM 64
#define H_DIM 1024
#define BATCH_N 1024

typedef unsigned long long u64;

__device__ __forceinline__ u64 pack2(float lo, float hi) {
    u64 r;
    asm("mov.b64 %0, {%1, %2};" : "=l"(r) : "f"(lo), "f"(hi));
    return r;
}
__device__ __forceinline__ void fma2(u64& d, u64 a, u64 b) {
    asm("fma.rn.f32x2 %0, %1, %2, %0;" : "+l"(d) : "l"(a), "l"(b));
}

// Normalized, transposed filterbanks. gamma folded into FyT.
// Read in the filt kernel via __ldg (L1-resident, broadcast-friendly).
__device__ float g_FyT[A_DIM * N_DIM];
__device__ float g_FxT[B_DIM * N_DIM];

__global__ void setup_kernel(const float* __restrict__ h,
                             const float* __restrict__ Ww,
                             const float* __restrict__ Wb) {
    __shared__ float red[256];
    __shared__ float s_params[5];
    __shared__ float s_scal[5];
    int tid = threadIdx.x;

    for (int i = 0; i < 5; i++) {
        float p = 0.f;
        for (int j = tid; j < H_DIM; j += 256) p += Ww[i * H_DIM + j] * h[j];
        red[tid] = p;
        __syncthreads();
        for (int s = 128; s > 0; s >>= 1) {
            if (tid < s) red[tid] += red[tid + s];
            __syncthreads();
        }
        if (tid == 0) s_params[i] = red[0] + Wb[i];
        __syncthreads();
    }

    if (tid == 0) {
        float gtX = s_params[0];
        float gtY = s_params[1];
        float var = expf(s_params[2] + 1e-8f);
        float dd  = expf(s_params[3]) * (float)(A_DIM - 1) / (float)(N_DIM - 1);
        float gamma = expf(s_params[4]);
        s_scal[0] = (float)(A_DIM + 1) * (gtX + 1.f) * 0.5f;
        s_scal[1] = (float)(B_DIM + 1) * (gtY + 1.f) * 0.5f;
        s_scal[2] = dd;
        s_scal[3] = 1.f / (2.f * var);
        s_scal[4] = gamma;
    }
    __syncthreads();
    float gX = s_scal[0], gY = s_scal[1], dd = s_scal[2];
    float i2v = s_scal[3], gamma = s_scal[4];

    float sx = 0.f, sy = 0.f;
    for (int idx = tid; idx < N_DIM * A_DIM; idx += 256) {
        int n = idx >> 7;
        int a = idx & 127;
        float off = ((float)n - (float)N_DIM * 0.5f - 0.5f) * dd;
        float muX = gX + off;
        float muY = gY + off;
        float da = (float)a - muX;
        float db = (float)a - muY;
        float fx = expf(-da * da * i2v);
        float fy = expf(-db * db * i2v);
        g_FxT[a * N_DIM + n] = fx;
        g_FyT[a * N_DIM + n] = fy;
        sx += fx;
        sy += fy;
    }
    red[tid] = sx;
    __syncthreads();
    for (int s = 128; s > 0; s >>= 1) {
        if (tid < s) red[tid] += red[tid + s];
        __syncthreads();
    }
    float sumX = red[0];
    __syncthreads();
    red[tid] = sy;
    __syncthreads();
    for (int s = 128; s > 0; s >>= 1) {
        if (tid < s) red[tid] += red[tid + s];
        __syncthreads();
    }
    float sumY = red[0];
    __syncthreads();

    float invX = 1.f / sumX;
    float invYg = gamma / sumY;
    for (int idx = tid; idx < N_DIM * A_DIM; idx += 256) {
        g_FxT[idx] *= invX;
        g_FyT[idx] *= invYg;
    }
}

#define TSTR 68
// smem floats: zs 16384 | tT 128*TSTR  (~98KB -> 2 blocks/SM, 4 warps/SMSP)
#define SMEM_FLOATS (16384 + 128 * TSTR)

__global__ __launch_bounds__(256, 2)
void filt_kernel(const float* __restrict__ x,
                 const float* __restrict__ xh,
                 float* __restrict__ out) {
    extern __shared__ float sm[];
    float* zs = sm;
    float* tT = sm + 16384;

    int k = blockIdx.x;
    int which = blockIdx.y;
    const float* src = (which == 0 ? x : xh) + (size_t)k * (A_DIM * B_DIM);
    int tid = threadIdx.x;

    // stage z (64KB) into smem, coalesced float4
    {
        const float4* s4 = (const float4*)src;
        float4* z4 = (float4*)zs;
#pragma unroll
        for (int i = 0; i < 16; i++) z4[tid + i * 256] = s4[tid + i * 256];
    }
    __syncthreads();

    // ---- Stage 1: t[n][b] = sum_a FyT[a][n] * z[a][b]  (packed over n) ----
    // z from smem; FyT via LDG (L1-resident, same addresses for every block).
    // thread tile 8n x 4b; tid bits: [1:0]=b-sub, [4:2]=n-tile, [7:5]=b-group
    {
        int b0 = (tid & 3) * 4 + (tid >> 5) * 16;
        int n0 = ((tid >> 2) & 7) * 8;

        const ulonglong2* fy0 = (const ulonglong2*)&g_FyT[n0];
        const ulonglong2* fy1 = (const ulonglong2*)&g_FyT[n0 + 4];

        u64 acc[4][4];  // [n-pair][b]
#pragma unroll
        for (int j = 0; j < 4; j++)
#pragma unroll
            for (int i = 0; i < 4; i++) acc[j][i] = 0ull;

#pragma unroll 4
        for (int a = 0; a < A_DIM; a++) {
            ulonglong2 f01 = __ldg(fy0 + a * 16);  // 64 floats per row = 16 ulonglong2
            ulonglong2 f23 = __ldg(fy1 + a * 16);
            float4 zv = *(const float4*)&zs[a * 128 + b0];
            u64 fp[4] = {f01.x, f01.y, f23.x, f23.y};
            u64 zb[4] = {pack2(zv.x, zv.x), pack2(zv.y, zv.y),
                         pack2(zv.z, zv.z), pack2(zv.w, zv.w)};
#pragma unroll
            for (int j = 0; j < 4; j++)
#pragma unroll
                for (int i = 0; i < 4; i++) fma2(acc[j][i], fp[j], zb[i]);
        }

        // store transposed: tT[b][n0..n0+7]
#pragma unroll
        for (int i = 0; i < 4; i++) {
            int row = b0 + i;
            ulonglong2 s0, s1;
            s0.x = acc[0][i]; s0.y = acc[1][i];
            s1.x = acc[2][i]; s1.y = acc[3][i];
            *(ulonglong2*)&tT[row * TSTR + n0] = s0;
            *(ulonglong2*)&tT[row * TSTR + n0 + 4] = s1;
        }
    }
    __syncthreads();

    // ---- Stage 2: out[n][m] = sum_b tT[b][n] * FxT[b][m]  (packed over m) ----
    {
        int m0 = (tid & 15) * 4;
        int n0 = (tid >> 4) * 4;

        const ulonglong2* fxp0 = (const ulonglong2*)&g_FxT[m0];

        u64 acc[4][2];
#pragma unroll
        for (int j = 0; j < 4; j++) {
            acc[j][0] = 0ull;
            acc[j][1] = 0ull;
        }

#pragma unroll 4
        for (int b = 0; b < B_DIM; b++) {
            float4 tv = *(const float4*)&tT[b * TSTR + n0];
            ulonglong2 fxp = __ldg(fxp0 + b * 16);
            u64 tp[4] = {pack2(tv.x, tv.x), pack2(tv.y, tv.y),
                         pack2(tv.z, tv.z), pack2(tv.w, tv.w)};
#pragma unroll
            for (int j = 0; j < 4; j++) {
                fma2(acc[j][0], tp[j], fxp.x);
                fma2(acc[j][1], tp[j], fxp.y);
            }
        }

        float* obase = out + (size_t)k * (2 * N_DIM * N_DIM) + which * (N_DIM * N_DIM);
#pragma unroll
        for (int j = 0; j < 4; j++) {
            ulonglong2 s;
            s.x = acc[j][0];
            s.y = acc[j][1];
            *(ulonglong2*)&obase[(n0 + j) * N_DIM + m0] = s;
        }
    }
}

extern "C" void kernel_launch(void* const* d_in, const int* in_sizes, int n_in,
                              void* d_out, int out_size) {
    const float* x  = (const float*)d_in[0];
    const float* xh = (const float*)d_in[1];
    const float* h  = (const float*)d_in[2];
    const float* Ww = (const float*)d_in[3];
    const float* Wb = (const float*)d_in[4];
    float* out = (float*)d_out;

    cudaFuncSetAttribute(filt_kernel, cudaFuncAttributeMaxDynamicSharedMemorySize,
                         SMEM_FLOATS * sizeof(float));

    setup_kernel<<<1, 256>>>(h, Ww, Wb);

    dim3 grid(BATCH_N, 2);
    filt_kernel<<<grid, 256, SMEM_FLOATS * sizeof(float)>>>(x, xh, out);
}

// round 6
// speedup vs baseline: 2.0623x; 2.0123x over previous
#include <cuda_runtime.h>
#include <cuda_bf16.h>
#include <stdint.h>

#define A_DIM 128
#define N_DIM 64
#define H_DIM 1024
#define NJOBS 2048

#define ZSTR 136   // bf16 elems per z row   (272B: 8 ldmatrix rows cover 32 banks)
#define FSTR 136   // filterbank row stride
#define TSTR2 72   // tT row stride (144B, same property)

// Filterbanks, bf16 hi/lo, padded natural layout [row][stride]
__device__ __align__(16) unsigned short g_FyH[64 * FSTR];
__device__ __align__(16) unsigned short g_FyL[64 * FSTR];
__device__ __align__(16) unsigned short g_FxH[64 * FSTR];
__device__ __align__(16) unsigned short g_FxL[64 * FSTR];

// ---------------- helpers ----------------
__device__ __forceinline__ uint32_t smem_u32(const void* p) {
    uint32_t a;
    asm("{ .reg .u64 t; cvta.to.shared.u64 t, %1; cvt.u32.u64 %0, t; }" : "=r"(a) : "l"(p));
    return a;
}
// pack two f32 -> bf16x2; first arg lands in bits[15:0]
__device__ __forceinline__ uint32_t pkbf(float lo, float hi) {
    uint32_t r;
    asm("cvt.rn.bf16x2.f32 %0, %1, %2;" : "=r"(r) : "f"(hi), "f"(lo));
    return r;
}
__device__ __forceinline__ void ldsm4(uint32_t a, uint32_t* r) {
    asm volatile("ldmatrix.sync.aligned.m8n8.x4.shared.b16 {%0,%1,%2,%3}, [%4];"
                 : "=r"(r[0]), "=r"(r[1]), "=r"(r[2]), "=r"(r[3]) : "r"(a));
}
__device__ __forceinline__ void ldsm4t(uint32_t a, uint32_t* r) {
    asm volatile("ldmatrix.sync.aligned.m8n8.x4.trans.shared.b16 {%0,%1,%2,%3}, [%4];"
                 : "=r"(r[0]), "=r"(r[1]), "=r"(r[2]), "=r"(r[3]) : "r"(a));
}
__device__ __forceinline__ void mma16816(float* c, const uint32_t* a, const uint32_t* b) {
    asm volatile(
        "mma.sync.aligned.m16n8k16.row.col.f32.bf16.bf16.f32 "
        "{%0,%1,%2,%3}, {%4,%5,%6,%7}, {%8,%9}, {%0,%1,%2,%3};"
        : "+f"(c[0]), "+f"(c[1]), "+f"(c[2]), "+f"(c[3])
        : "r"(a[0]), "r"(a[1]), "r"(a[2]), "r"(a[3]), "r"(b[0]), "r"(b[1]));
}

// ---------------- setup: params -> split filterbanks ----------------
__global__ void setup_kernel(const float* __restrict__ h,
                             const float* __restrict__ Ww,
                             const float* __restrict__ Wb) {
    __shared__ float red[256];
    __shared__ float s_params[5];
    __shared__ float s_scal[5];
    int tid = threadIdx.x;

    for (int i = 0; i < 5; i++) {
        float p = 0.f;
        for (int j = tid; j < H_DIM; j += 256) p += Ww[i * H_DIM + j] * h[j];
        red[tid] = p;
        __syncthreads();
        for (int s = 128; s > 0; s >>= 1) {
            if (tid < s) red[tid] += red[tid + s];
            __syncthreads();
        }
        if (tid == 0) s_params[i] = red[0] + Wb[i];
        __syncthreads();
    }

    if (tid == 0) {
        float gtX = s_params[0];
        float gtY = s_params[1];
        float var = expf(s_params[2] + 1e-8f);
        float dd  = expf(s_params[3]) * (float)(A_DIM - 1) / (float)(N_DIM - 1);
        float gamma = expf(s_params[4]);
        s_scal[0] = (float)(A_DIM + 1) * (gtX + 1.f) * 0.5f;
        s_scal[1] = (float)(A_DIM + 1) * (gtY + 1.f) * 0.5f;
        s_scal[2] = dd;
        s_scal[3] = 1.f / (2.f * var);
        s_scal[4] = gamma;
    }
    __syncthreads();
    float gX = s_scal[0], gY = s_scal[1], dd = s_scal[2];
    float i2v = s_scal[3], gamma = s_scal[4];

    float sx = 0.f, sy = 0.f;
    for (int idx = tid; idx < N_DIM * A_DIM; idx += 256) {
        int n = idx >> 7, a = idx & 127;
        float off = ((float)n - (float)N_DIM * 0.5f - 0.5f) * dd;
        float da = (float)a - (gX + off);
        float db = (float)a - (gY + off);
        sx += expf(-da * da * i2v);
        sy += expf(-db * db * i2v);
    }
    red[tid] = sx;
    __syncthreads();
    for (int s = 128; s > 0; s >>= 1) { if (tid < s) red[tid] += red[tid + s]; __syncthreads(); }
    float sumX = red[0];
    __syncthreads();
    red[tid] = sy;
    __syncthreads();
    for (int s = 128; s > 0; s >>= 1) { if (tid < s) red[tid] += red[tid + s]; __syncthreads(); }
    float sumY = red[0];
    __syncthreads();

    float invX = 1.f / sumX;
    float invYg = gamma / sumY;

    for (int idx = tid; idx < N_DIM * A_DIM; idx += 256) {
        int n = idx >> 7, a = idx & 127;
        float off = ((float)n - (float)N_DIM * 0.5f - 0.5f) * dd;
        float da = (float)a - (gX + off);
        float db = (float)a - (gY + off);
        float fy = expf(-db * db * i2v) * invYg;  // gamma folded
        float fx = expf(-da * da * i2v) * invX;

        unsigned short yh = __bfloat16_as_ushort(__float2bfloat16(fy));
        float yhf = __uint_as_float(((uint32_t)yh) << 16);
        unsigned short yl = __bfloat16_as_ushort(__float2bfloat16(fy - yhf));
        unsigned short xhb = __bfloat16_as_ushort(__float2bfloat16(fx));
        float xhf = __uint_as_float(((uint32_t)xhb) << 16);
        unsigned short xl = __bfloat16_as_ushort(__float2bfloat16(fx - xhf));

        g_FyH[n * FSTR + a] = yh;
        g_FyL[n * FSTR + a] = yl;
        g_FxH[n * FSTR + a] = xhb;
        g_FxL[n * FSTR + a] = xl;
    }
}

// ---------------- SMEM layout (bytes) ----------------
#define SM_ZH   0
#define SM_ZL   34816
#define SM_TH   69632
#define SM_TL   88064
#define SM_FYH  106496
#define SM_FYL  123904
#define SM_FXH  141312
#define SM_FXL  158720
#define SM_TOTAL 176128

__global__ __launch_bounds__(256, 1)
void filt_mma(const float* __restrict__ x, const float* __restrict__ xh,
              float* __restrict__ out, int gridn) {
    extern __shared__ char sm[];
    int tid = threadIdx.x;
    int wid = tid >> 5, lane = tid & 31;
    int grp = lane >> 3, li = lane & 7;
    int qt = lane >> 2;          // t/4 : fragment row group
    int qr = (lane & 3) * 2;     // 2*(t%4) : fragment col pair

    // stage split filterbanks once per CTA
    {
        const uint4* s;
        uint4* d;
        s = (const uint4*)g_FyH; d = (uint4*)(sm + SM_FYH);
        for (int i = tid; i < 1088; i += 256) d[i] = s[i];
        s = (const uint4*)g_FyL; d = (uint4*)(sm + SM_FYL);
        for (int i = tid; i < 1088; i += 256) d[i] = s[i];
        s = (const uint4*)g_FxH; d = (uint4*)(sm + SM_FXH);
        for (int i = tid; i < 1088; i += 256) d[i] = s[i];
        s = (const uint4*)g_FxL; d = (uint4*)(sm + SM_FXL);
        for (int i = tid; i < 1088; i += 256) d[i] = s[i];
    }

    uint32_t sb = smem_u32(sm);

    // lane-constant ldmatrix byte offsets
    int radd = (grp >> 1) * 8;   // +8 rows for matrices 2,3
    int cadd = (grp & 1) * 8;    // +8 cols for matrices 1,3

    // stage 1 A (z, stride ZSTR): warp owns b-rows b0w..b0w+15
    int b0w = wid * 16;
    uint32_t offA1 = (uint32_t)(((li + radd) * ZSTR + b0w + cadd) * 2);
    // stage 1 B (fy, stride FSTR): 4 x4-loads cover n=0..63
    uint32_t offB1[4];
#pragma unroll
    for (int q = 0; q < 4; q++)
        offB1[q] = (uint32_t)(((16 * q + li + radd) * FSTR + cadd) * 2);

    // stage 2: warp -> n-strip & m-half
    int n0 = (wid >> 1) * 16;
    int m0 = (wid & 1) * 32;
    uint32_t offA2 = (uint32_t)(((li + radd) * TSTR2 + n0 + cadd) * 2);
    uint32_t offB2[2];
#pragma unroll
    for (int q = 0; q < 2; q++)
        offB2[q] = (uint32_t)(((m0 + 16 * q + li + radd) * FSTR + cadd) * 2);

    __syncthreads();

    for (int job = blockIdx.x; job < NJOBS; job += gridn) {
        int which = job >> 10;
        int img = job & 1023;
        const float* src = (which ? xh : x) + (size_t)img * (A_DIM * A_DIM);

        // ---- 1. z -> smem bf16 hi/lo, padded [a][b] ----
        {
            const float4* s4 = (const float4*)src;
#pragma unroll
            for (int i = 0; i < 16; i++) {
                int e4 = tid + (i << 8);
                float4 v = __ldg(s4 + e4);
                int e = e4 << 2;
                int a = e >> 7, b = e & 127;
                uint32_t hA = pkbf(v.x, v.y), hB = pkbf(v.z, v.w);
                float l0 = v.x - __uint_as_float(hA << 16);
                float l1 = v.y - __uint_as_float(hA & 0xFFFF0000u);
                float l2 = v.z - __uint_as_float(hB << 16);
                float l3 = v.w - __uint_as_float(hB & 0xFFFF0000u);
                uint32_t lA = pkbf(l0, l1), lB = pkbf(l2, l3);
                uint32_t boff = (uint32_t)((a * ZSTR + b) * 2);
                *(uint2*)(sm + SM_ZH + boff) = make_uint2(hA, hB);
                *(uint2*)(sm + SM_ZL + boff) = make_uint2(lA, lB);
            }
        }
        __syncthreads();

        // ---- 2. stage 1: tT[b][n] = sum_a z[a][b]*Fy[n][a] (3-term split) ----
        {
            float acc[8][4];
#pragma unroll
            for (int j = 0; j < 8; j++)
#pragma unroll
                for (int c = 0; c < 4; c++) acc[j][c] = 0.f;

#pragma unroll
            for (int s = 0; s < 8; s++) {
                uint32_t Ah[4], Al[4], Bh[16], Bl[16];
                uint32_t aoff = offA1 + (uint32_t)(s * 16 * ZSTR * 2);
                ldsm4t(sb + SM_ZH + aoff, Ah);
                ldsm4t(sb + SM_ZL + aoff, Al);
#pragma unroll
                for (int q = 0; q < 4; q++) {
                    uint32_t boff = offB1[q] + (uint32_t)(s * 32);
                    ldsm4(sb + SM_FYH + boff, Bh + 4 * q);
                    ldsm4(sb + SM_FYL + boff, Bl + 4 * q);
                }
#pragma unroll
                for (int j = 0; j < 8; j++) {
                    mma16816(acc[j], Ah, Bh + 2 * j);
                    mma16816(acc[j], Ah, Bl + 2 * j);
                    mma16816(acc[j], Al, Bh + 2 * j);
                }
            }

            // write tT hi/lo
            int r0 = b0w + qt, r1 = r0 + 8;
#pragma unroll
            for (int j = 0; j < 8; j++) {
                int nj = 8 * j + qr;
                uint32_t h01 = pkbf(acc[j][0], acc[j][1]);
                float d0 = acc[j][0] - __uint_as_float(h01 << 16);
                float d1 = acc[j][1] - __uint_as_float(h01 & 0xFFFF0000u);
                uint32_t l01 = pkbf(d0, d1);
                uint32_t h23 = pkbf(acc[j][2], acc[j][3]);
                float d2 = acc[j][2] - __uint_as_float(h23 << 16);
                float d3 = acc[j][3] - __uint_as_float(h23 & 0xFFFF0000u);
                uint32_t l23 = pkbf(d2, d3);
                *(uint32_t*)(sm + SM_TH + (r0 * TSTR2 + nj) * 2) = h01;
                *(uint32_t*)(sm + SM_TL + (r0 * TSTR2 + nj) * 2) = l01;
                *(uint32_t*)(sm + SM_TH + (r1 * TSTR2 + nj) * 2) = h23;
                *(uint32_t*)(sm + SM_TL + (r1 * TSTR2 + nj) * 2) = l23;
            }
        }
        __syncthreads();

        // ---- 3. stage 2: C[n][m] = sum_b t[n][b]*Fx[m][b] (3-term split) ----
        {
            float acc[4][4];
#pragma unroll
            for (int j = 0; j < 4; j++)
#pragma unroll
                for (int c = 0; c < 4; c++) acc[j][c] = 0.f;

#pragma unroll
            for (int s = 0; s < 8; s++) {
                uint32_t Ah[4], Al[4], Bh[8], Bl[8];
                uint32_t aoff = offA2 + (uint32_t)(s * 16 * TSTR2 * 2);
                ldsm4t(sb + SM_TH + aoff, Ah);
                ldsm4t(sb + SM_TL + aoff, Al);
#pragma unroll
                for (int q = 0; q < 2; q++) {
                    uint32_t boff = offB2[q] + (uint32_t)(s * 32);
                    ldsm4(sb + SM_FXH + boff, Bh + 4 * q);
                    ldsm4(sb + SM_FXL + boff, Bl + 4 * q);
                }
#pragma unroll
                for (int j = 0; j < 4; j++) {
                    mma16816(acc[j], Ah, Bh + 2 * j);
                    mma16816(acc[j], Ah, Bl + 2 * j);
                    mma16816(acc[j], Al, Bh + 2 * j);
                }
            }

            float* ob = out + (size_t)img * (2 * N_DIM * N_DIM) + which * (N_DIM * N_DIM);
            int nA = n0 + qt, nB = nA + 8;
#pragma unroll
            for (int j = 0; j < 4; j++) {
                int m = m0 + 8 * j + qr;
                *(float2*)(ob + nA * N_DIM + m) = make_float2(acc[j][0], acc[j][1]);
                *(float2*)(ob + nB * N_DIM + m) = make_float2(acc[j][2], acc[j][3]);
            }
        }
        __syncthreads();
    }
}

extern "C" void kernel_launch(void* const* d_in, const int* in_sizes, int n_in,
                              void* d_out, int out_size) {
    const float* x  = (const float*)d_in[0];
    const float* xh = (const float*)d_in[1];
    const float* h  = (const float*)d_in[2];
    const float* Ww = (const float*)d_in[3];
    const float* Wb = (const float*)d_in[4];
    float* out = (float*)d_out;

    int sms = 148;
    cudaDeviceGetAttribute(&sms, cudaDevAttrMultiProcessorCount, 0);
    if (sms <= 0) sms = 148;

    cudaFuncSetAttribute(filt_mma, cudaFuncAttributeMaxDynamicSharedMemorySize, SM_TOTAL);

    setup_kernel<<<1, 256>>>(h, Ww, Wb);
    filt_mma<<<sms, 256, SM_TOTAL>>>(x, xh, out, sms);
}